// round 7
// baseline (speedup 1.0000x reference)
#include <cuda_runtime.h>
#include <cuda_fp16.h>
#include <math.h>
#include <stdint.h>

// ===========================================================================
// StreamingSSMCell (B=8192, D=1024, DCONV=4) — fp16 mma.sync (m16n8k16)
//   Legacy tensor unit measured issue-limited at ~27 TF/s on k8 tf32;
//   k16 fp16 doubles FLOP/instruction. fp16 mantissa == tf32 mantissa (10b),
//   measured tf32 rel_err 3.95e-4 -> fp16 predicted ~4-6e-4 < 1e-3.
//   d_out layout: [ out (B*D) | h_new (B*D) | new_buf (B*D*4) ]
// ===========================================================================

#define D_MODEL 1024
#define TWO_D   2048
#define BATCH   8192

__device__ float  g_xz [(size_t)BATCH * TWO_D];    // in_proj output (fp32)
__device__ __half g_xh [(size_t)BATCH * D_MODEL];  // x in fp16
__device__ __half g_gh [(size_t)BATCH * D_MODEL];  // gated act in fp16
__device__ __half g_wih[(size_t)TWO_D * D_MODEL];  // W_in fp16
__device__ __half g_woh[(size_t)D_MODEL * D_MODEL];// W_out fp16

// ------------------------------ GEMM config --------------------------------
#define BM 128
#define BN 128
#define BK 32                       // halves per k-tile
#define KPAD_H 40                   // padded halves per row (80 B)
#define NTHREADS 256                // 8 warps = 2 (m) x 4 (n), warp tile 64x32
#define NSTAGE 3
#define A_TILE_BYTES (BM * KPAD_H * 2)              // 10240
#define STAGE_BYTES  (2 * A_TILE_BYTES)             // 20480
#define SMEM_BYTES   (NSTAGE * STAGE_BYTES)         // 61440

// ------------------------------ PTX helpers --------------------------------
__device__ __forceinline__ uint32_t smem_u32(const void* p) {
    uint32_t a;
    asm("{ .reg .u64 t; cvta.to.shared.u64 t, %1; cvt.u32.u64 %0, t; }"
        : "=r"(a) : "l"(p));
    return a;
}

#define CP_ASYNC16(dst, src) \
    asm volatile("cp.async.cg.shared.global [%0], [%1], 16;" :: "r"(dst), "l"(src))
#define CP_ASYNC_COMMIT() asm volatile("cp.async.commit_group;" ::: "memory")
#define CP_ASYNC_WAIT1()  asm volatile("cp.async.wait_group 1;" ::: "memory")

#define LDSM_X4(r0, r1, r2, r3, addr)                                          \
    asm volatile("ldmatrix.sync.aligned.m8n8.x4.shared.b16 {%0,%1,%2,%3}, [%4];" \
        : "=r"(r0), "=r"(r1), "=r"(r2), "=r"(r3) : "r"(addr))

#define MMA_F16(c, a, b)                                                       \
    asm volatile("mma.sync.aligned.m16n8k16.row.col.f32.f16.f16.f32 "          \
        "{%0,%1,%2,%3}, {%4,%5,%6,%7}, {%8,%9}, {%0,%1,%2,%3};"                \
        : "+f"((c)[0]), "+f"((c)[1]), "+f"((c)[2]), "+f"((c)[3])               \
        : "r"((a)[0]), "r"((a)[1]), "r"((a)[2]), "r"((a)[3]),                  \
          "r"((b)[0]), "r"((b)[1]))

// ------------------------- fp16 mma.sync GEMM ------------------------------
// C[m,n] = sum_k A[m,k]*Bm[n,k] + bias[n]; A [M,K] lda, Bm [N,K] ldb (K-major,
// fp16). grid = (N/128, M/128), 256 threads. Warp (wm, wn) owns 64x32.
__global__ __launch_bounds__(NTHREADS, 2)
void gemm_f16(const __half* __restrict__ A, int lda,
              const __half* __restrict__ Bm, int ldb,
              const float* __restrict__ bias,
              float* __restrict__ C, int ldc, int K)
{
    extern __shared__ char smem[];
    const uint32_t sbase = smem_u32(smem);
    const int tid  = threadIdx.x;
    const int lane = tid & 31;
    const int wid  = tid >> 5;
    const int wm = wid >> 2;            // 0..1
    const int wn = wid & 3;             // 0..3
    const int g  = lane >> 2;
    const int tg = lane & 3;
    const int m0 = blockIdx.y * BM;
    const int n0 = blockIdx.x * BN;

    // global chunk mapping: id = tid + q*256 -> row = id>>2, c = id&3 (8 halves)
    const int gr = tid >> 2;            // handled rows: gr, gr+64
    const int gc = tid & 3;
    const __half* gA0 = A  + (size_t)(m0 + gr)      * lda + gc * 8;
    const __half* gA1 = A  + (size_t)(m0 + gr + 64) * lda + gc * 8;
    const __half* gB0 = Bm + (size_t)(n0 + gr)      * ldb + gc * 8;
    const __half* gB1 = Bm + (size_t)(n0 + gr + 64) * ldb + gc * 8;
    const uint32_t sA0 = gr * 80 + gc * 16;
    const uint32_t sA1 = (gr + 64) * 80 + gc * 16;

    // ldmatrix byte offsets within stage
    uint32_t a_off[4];
    #pragma unroll
    for (int i = 0; i < 4; i++) {
        const int row = wm * 64 + i * 16 + (lane & 15);
        a_off[i] = (uint32_t)(row * 80 + (lane >> 4) * 16);
    }
    uint32_t b_off[2];
    #pragma unroll
    for (int j = 0; j < 2; j++) {
        const int row = wn * 32 + j * 16 + ((lane >> 4) << 3) + (lane & 7);
        b_off[j] = (uint32_t)(A_TILE_BYTES + row * 80 + ((lane >> 3) & 1) * 16);
    }

    float acc[4][4][4];
    #pragma unroll
    for (int i = 0; i < 4; i++)
        #pragma unroll
        for (int j = 0; j < 4; j++)
            #pragma unroll
            for (int r = 0; r < 4; r++) acc[i][j][r] = 0.0f;

    const int T = K / BK;

    #define LOAD_STAGE(t) do {                                                 \
        const uint32_t _s = sbase + ((t) % NSTAGE) * STAGE_BYTES;              \
        const size_t _ko = (size_t)(t) * BK;                                   \
        CP_ASYNC16(_s + sA0, gA0 + _ko);                                       \
        CP_ASYNC16(_s + sA1, gA1 + _ko);                                       \
        CP_ASYNC16(_s + A_TILE_BYTES + sA0, gB0 + _ko);                        \
        CP_ASYNC16(_s + A_TILE_BYTES + sA1, gB1 + _ko);                        \
        CP_ASYNC_COMMIT();                                                     \
    } while (0)

    LOAD_STAGE(0);
    LOAD_STAGE(1);

    for (int t = 0; t < T; t++) {
        CP_ASYNC_WAIT1();
        __syncthreads();

        if (t + 2 < T) { LOAD_STAGE(t + 2); } else { CP_ASYNC_COMMIT(); }

        const uint32_t st = sbase + (t % NSTAGE) * STAGE_BYTES;

        #pragma unroll
        for (int ks = 0; ks < 2; ks++) {           // two k16 steps per BK=32
            const uint32_t kb = ks * 32;           // 16 halves = 32 bytes
            uint32_t af[4][4], bf[4][2];
            #pragma unroll
            for (int i = 0; i < 4; i++)
                LDSM_X4(af[i][0], af[i][1], af[i][2], af[i][3],
                        st + a_off[i] + kb);
            #pragma unroll
            for (int j = 0; j < 2; j++)
                LDSM_X4(bf[2 * j][0], bf[2 * j][1],
                        bf[2 * j + 1][0], bf[2 * j + 1][1],
                        st + b_off[j] + kb);
            #pragma unroll
            for (int i = 0; i < 4; i++)
                #pragma unroll
                for (int j = 0; j < 4; j++)
                    MMA_F16(acc[i][j], af[i], bf[j]);
        }
    }
    #undef LOAD_STAGE

    // epilogue: add bias, store fp32
    #pragma unroll
    for (int j = 0; j < 4; j++) {
        const int col = n0 + wn * 32 + j * 8 + tg * 2;
        const float2 bb = *(const float2*)(bias + col);
        #pragma unroll
        for (int i = 0; i < 4; i++) {
            const int r0 = m0 + wm * 64 + i * 16 + g;
            float2 v0; v0.x = acc[i][j][0] + bb.x; v0.y = acc[i][j][1] + bb.y;
            *(float2*)(C + (size_t)r0 * ldc + col) = v0;
            float2 v1; v1.x = acc[i][j][2] + bb.x; v1.y = acc[i][j][3] + bb.y;
            *(float2*)(C + (size_t)(r0 + 8) * ldc + col) = v1;
        }
    }
}

// --------------------------- fp32 -> fp16 convert ---------------------------
__global__ void f2h_kernel(const float* __restrict__ in,
                           __half* __restrict__ out, int n8)
{
    const int i = blockIdx.x * blockDim.x + threadIdx.x;
    if (i >= n8) return;
    const float4 v0 = ((const float4*)in)[2 * i];
    const float4 v1 = ((const float4*)in)[2 * i + 1];
    __half2 h[4];
    h[0] = __floats2half2_rn(v0.x, v0.y);
    h[1] = __floats2half2_rn(v0.z, v0.w);
    h[2] = __floats2half2_rn(v1.x, v1.y);
    h[3] = __floats2half2_rn(v1.z, v1.w);
    ((uint4*)out)[i] = *(const uint4*)h;
}

// ------------------------ fused elementwise stage ---------------------------
__device__ __forceinline__ float silu_f(float x) { return x / (1.0f + expf(-x)); }

__global__ void fused_elementwise(const float* __restrict__ xz,
                                  const float* __restrict__ h,
                                  const float* __restrict__ conv_buf,
                                  const float* __restrict__ conv_w,
                                  const float* __restrict__ conv_b,
                                  float* __restrict__ out_hnew,
                                  float* __restrict__ out_newbuf,
                                  __half* __restrict__ g_out,
                                  int B, int D)
{
    const int idx = blockIdx.x * blockDim.x + threadIdx.x;
    if (idx >= B * D) return;
    const int b = idx / D;
    const int d = idx - b * D;

    const float xi = xz[(size_t)b * 2 * D + d];
    const float z  = xz[(size_t)b * 2 * D + D + d];

    const float4 cb = *(const float4*)(conv_buf + (size_t)idx * 4);
    const float4 cw = *(const float4*)(conv_w + (size_t)d * 4);

    float co = cb.y * cw.x + cb.z * cw.y + cb.w * cw.z + xi * cw.w + conv_b[d];
    co = silu_f(co);

    const float lmin = 2.302585092994046f;   // log(10)
    const float lmax = 7.600902459542082f;   // log(2000)
    const float t = lmin + (float)d * (lmax - lmin) / (float)(D - 1);
    const float dec = expf(-expf(-t));

    const float hn = dec * h[idx] + (1.0f - dec) * co;

    out_hnew[idx] = hn;
    float4 nb; nb.x = cb.y; nb.y = cb.z; nb.z = cb.w; nb.w = xi;
    *(float4*)(out_newbuf + (size_t)idx * 4) = nb;

    g_out[idx] = __float2half_rn(hn * silu_f(z));
}

// ------------------------------- launch ------------------------------------
extern "C" void kernel_launch(void* const* d_in, const int* in_sizes, int n_in,
                              void* d_out, int out_size)
{
    const float* x        = (const float*)d_in[0];
    const float* h        = (const float*)d_in[1];
    const float* conv_buf = (const float*)d_in[2];
    const float* W_in     = (const float*)d_in[3];
    const float* b_in     = (const float*)d_in[4];
    const float* conv_w   = (const float*)d_in[5];
    const float* conv_b   = (const float*)d_in[6];
    const float* W_out    = (const float*)d_in[7];
    const float* b_out    = (const float*)d_in[8];

    const int D = in_sizes[6];
    const int B = in_sizes[0] / D;
    const int twoD = in_sizes[4];

    float* out      = (float*)d_out;
    float* out_hnew = out + (size_t)B * D;
    float* out_nbuf = out + (size_t)2 * B * D;

    cudaFuncSetAttribute(gemm_f16, cudaFuncAttributeMaxDynamicSharedMemorySize,
                         SMEM_BYTES);

    // converts to fp16
    {
        int n8 = B * D / 8;
        f2h_kernel<<<(n8 + 255) / 256, 256>>>(x, g_xh, n8);
        n8 = twoD * D / 8;
        f2h_kernel<<<(n8 + 255) / 256, 256>>>(W_in, g_wih, n8);
        n8 = D * D / 8;
        f2h_kernel<<<(n8 + 255) / 256, 256>>>(W_out, g_woh, n8);
    }

    // GEMM1: xz = x @ W_in^T + b_in   [B, 2D]
    {
        dim3 grid(twoD / BN, B / BM);
        gemm_f16<<<grid, NTHREADS, SMEM_BYTES>>>(g_xh, D, g_wih, D, b_in,
                                                 g_xz, twoD, D);
    }

    // fused elementwise (emits g in fp16)
    {
        const int n = B * D;
        fused_elementwise<<<(n + 255) / 256, 256>>>(
            g_xz, h, conv_buf, conv_w, conv_b, out_hnew, out_nbuf, g_gh, B, D);
    }

    // GEMM2: out = g @ W_out^T + b_out  [B, D]
    {
        dim3 grid(D / BN, B / BM);
        gemm_f16<<<grid, NTHREADS, SMEM_BYTES>>>(g_gh, D, g_woh, D, b_out,
                                                 out, D, D);
    }
}

// round 8
// speedup vs baseline: 1.7925x; 1.7925x over previous
#include <cuda_runtime.h>
#include <math.h>
#include <stdint.h>

// ===========================================================================
// StreamingSSMCell (B=8192, D=1024, DCONV=4) — HYBRID GEMM:
//   warps 0-7 : tf32 mma.sync (ldmatrix) on N-cols [0,128)   (~27 TF/s pipe)
//   warps 8-15: fp32 FFMA SIMT        on N-cols [128,256)    (~36 TF/s pipe)
//   Both pipes measured independently saturated; run them concurrently.
//   d_out layout: [ out (B*D) | h_new (B*D) | new_buf (B*D*4) ]
// ===========================================================================

#define D_MODEL 1024
#define TWO_D   2048
#define BATCH   8192

__device__ float g_xz[(size_t)BATCH * TWO_D];
__device__ float g_g [(size_t)BATCH * D_MODEL];

// ------------------------------ GEMM config --------------------------------
#define BM 128
#define BN 256
#define BK 32
#define KPAD 36            // tensor tiles: floats per row (144 B, 16B-aligned)
#define ASTR 132           // fma tiles: floats per row
#define NTH  512

#define OFF_AT 0
#define OFF_BT (128 * KPAD)                  // 4608 words
#define OFF_AF (OFF_BT + 128 * KPAD)         // 9216
#define OFF_BF (OFF_AF + BK * ASTR)          // 13440
#define STAGE_W (OFF_BF + BK * ASTR)         // 17664 words
#define SMEM_BYTES (2 * STAGE_W * 4)         // 141312 B

// ------------------------------ PTX helpers --------------------------------
__device__ __forceinline__ uint32_t smem_u32(const void* p) {
    uint32_t a;
    asm("{ .reg .u64 t; cvta.to.shared.u64 t, %1; cvt.u32.u64 %0, t; }"
        : "=r"(a) : "l"(p));
    return a;
}

#define CP_ASYNC16(dst, src) \
    asm volatile("cp.async.cg.shared.global [%0], [%1], 16;" :: "r"(dst), "l"(src))
#define CP_ASYNC_COMMIT()   asm volatile("cp.async.commit_group;" ::: "memory")
#define CP_ASYNC_WAIT_ALL() asm volatile("cp.async.wait_group 0;" ::: "memory")

__device__ __forceinline__ uint32_t rna(uint32_t x) {
    uint32_t r;
    asm("cvt.rna.tf32.f32 %0, %1;" : "=r"(r) : "f"(__uint_as_float(x)));
    return r;
}

#define LDSM_X4(r0, r1, r2, r3, addr)                                          \
    asm volatile("ldmatrix.sync.aligned.m8n8.x4.shared.b16 {%0,%1,%2,%3}, [%4];" \
        : "=r"(r0), "=r"(r1), "=r"(r2), "=r"(r3) : "r"(addr))

#define MMA_TF32(c, a, b)                                                      \
    asm volatile("mma.sync.aligned.m16n8k8.row.col.f32.tf32.tf32.f32 "         \
        "{%0,%1,%2,%3}, {%4,%5,%6,%7}, {%8,%9}, {%0,%1,%2,%3};"                \
        : "+f"((c)[0]), "+f"((c)[1]), "+f"((c)[2]), "+f"((c)[3])               \
        : "r"((a)[0]), "r"((a)[1]), "r"((a)[2]), "r"((a)[3]),                  \
          "r"((b)[0]), "r"((b)[1]))

// --------------------------- hybrid GEMM kernel -----------------------------
// C[m,n] = sum_k A[m,k]*Bm[n,k] + bias[n]; A [M,K] lda, Bm [N,K] ldb (K-major)
// grid = (N/256, M/128), 512 threads.
__global__ __launch_bounds__(NTH, 1)
void gemm_hybrid(const float* __restrict__ A, int lda,
                 const float* __restrict__ Bm, int ldb,
                 const float* __restrict__ bias,
                 float* __restrict__ C, int ldc, int K)
{
    extern __shared__ float smem[];
    const uint32_t sbase = smem_u32(smem);
    const int tid  = threadIdx.x;
    const int lane = tid & 31;
    const int wid  = tid >> 5;
    const int m0 = blockIdx.y * BM;
    const int n0 = blockIdx.x * BN;
    const int T = K / BK;

    // ---- loader mapping (all 512 threads): rows lr, lr+64; chunk lc
    const int lr = tid >> 3;             // 0..63
    const int lc = tid & 7;              // 0..7 (4-float chunk)

    // ---- tensor-side constants (warps 0..7): wm x wn = 2 x 4, 64x32 each
    const int wm = (wid >> 2) & 1;
    const int wn = wid & 3;
    const int g  = lane >> 2;
    const int tg = lane & 3;
    uint32_t a_boff[4], b_boff[2];
    #pragma unroll
    for (int i = 0; i < 4; i++) {
        const int row = wm * 64 + i * 16 + (lane & 15);
        a_boff[i] = (uint32_t)((OFF_AT + row * KPAD + ((lane >> 4) << 2)) * 4);
    }
    #pragma unroll
    for (int j = 0; j < 2; j++) {
        const int row = wn * 32 + j * 16 + ((lane >> 4) << 3) + (lane & 7);
        b_boff[j] = (uint32_t)((OFF_BT + row * KPAD + (((lane >> 3) & 1) << 2)) * 4);
    }

    // ---- fma-side constants (warps 8..15): 128x128, 8x8 per thread
    const int ftid = tid & 255;
    const int tx = ftid & 15;            // cols {tx*4..+3} u {64+tx*4..+3}
    const int ty = ftid >> 4;            // rows ty*8..+7

    // unified accumulator: tensor uses [ (i*4+j)*4 + r ], fma uses [ i*8+j ]
    float acc[64];
    #pragma unroll
    for (int i = 0; i < 64; i++) acc[i] = 0.0f;

    float4 ra[2], rb[2];

    #define CPLOAD(t, buf) do {                                                \
        const uint32_t _s = sbase + (buf) * (STAGE_W * 4);                     \
        _Pragma("unroll")                                                      \
        for (int _q = 0; _q < 2; _q++) {                                       \
            const int _r = lr + _q * 64;                                       \
            CP_ASYNC16(_s + (uint32_t)((OFF_AT + _r * KPAD + lc * 4) * 4),     \
                       A + (size_t)(m0 + _r) * lda + (size_t)(t) * BK + lc * 4);\
            CP_ASYNC16(_s + (uint32_t)((OFF_BT + _r * KPAD + lc * 4) * 4),     \
                       Bm + (size_t)(n0 + _r) * ldb + (size_t)(t) * BK + lc * 4);\
        }                                                                      \
        CP_ASYNC_COMMIT();                                                     \
    } while (0)

    #define LDGF(t) do {                                                       \
        _Pragma("unroll")                                                      \
        for (int _q = 0; _q < 2; _q++) {                                       \
            const int _r = lr + _q * 64;                                       \
            ra[_q] = *(const float4*)(A + (size_t)(m0 + _r) * lda              \
                                        + (size_t)(t) * BK + lc * 4);          \
            rb[_q] = *(const float4*)(Bm + (size_t)(n0 + 128 + _r) * ldb      \
                                        + (size_t)(t) * BK + lc * 4);          \
        }                                                                      \
    } while (0)

    #define STSF(buf) do {                                                     \
        float* _sf = smem + (buf) * STAGE_W;                                   \
        _Pragma("unroll")                                                      \
        for (int _q = 0; _q < 2; _q++) {                                       \
            const int _r = lr + _q * 64;                                       \
            _Pragma("unroll")                                                  \
            for (int _j = 0; _j < 4; _j++) {                                   \
                _sf[OFF_AF + (lc * 4 + _j) * ASTR + _r] = ((const float*)&ra[_q])[_j]; \
                _sf[OFF_BF + (lc * 4 + _j) * ASTR + _r] = ((const float*)&rb[_q])[_j]; \
            }                                                                  \
        }                                                                      \
    } while (0)

    // prologue: stage 0
    LDGF(0);
    CPLOAD(0, 0);
    STSF(0);
    CP_ASYNC_WAIT_ALL();
    __syncthreads();

    for (int t = 0; t < T; t++) {
        const int buf = t & 1;

        if (t + 1 < T) {
            LDGF(t + 1);
            CPLOAD(t + 1, buf ^ 1);
        }

        if (wid < 8) {
            // ------------- tensor half: cols [n0, n0+128) -------------
            const uint32_t st = sbase + buf * (STAGE_W * 4);
            #pragma unroll
            for (int ks = 0; ks < 4; ks++) {
                const uint32_t kb = (uint32_t)(ks * 32);   // 8 floats
                uint32_t af[4][4], bf[4][2];
                #pragma unroll
                for (int i = 0; i < 4; i++)
                    LDSM_X4(af[i][0], af[i][1], af[i][2], af[i][3],
                            st + a_boff[i] + kb);
                #pragma unroll
                for (int j = 0; j < 2; j++)
                    LDSM_X4(bf[2 * j][0], bf[2 * j][1],
                            bf[2 * j + 1][0], bf[2 * j + 1][1],
                            st + b_boff[j] + kb);
                #pragma unroll
                for (int i = 0; i < 4; i++)
                    #pragma unroll
                    for (int q = 0; q < 4; q++) af[i][q] = rna(af[i][q]);
                #pragma unroll
                for (int j = 0; j < 4; j++) {
                    bf[j][0] = rna(bf[j][0]);
                    bf[j][1] = rna(bf[j][1]);
                }
                #pragma unroll
                for (int i = 0; i < 4; i++)
                    #pragma unroll
                    for (int j = 0; j < 4; j++)
                        MMA_TF32((acc + (i * 4 + j) * 4), af[i], bf[j]);
            }
        } else {
            // ------------- fma half: cols [n0+128, n0+256) -------------
            const float* fA = smem + buf * STAGE_W + OFF_AF;
            const float* fB = smem + buf * STAGE_W + OFF_BF;
            #pragma unroll 8
            for (int k = 0; k < BK; k++) {
                const float4 a0 = *(const float4*)(fA + k * ASTR + ty * 8);
                const float4 a1 = *(const float4*)(fA + k * ASTR + ty * 8 + 4);
                const float4 b0 = *(const float4*)(fB + k * ASTR + tx * 4);
                const float4 b1 = *(const float4*)(fB + k * ASTR + 64 + tx * 4);
                const float av[8] = {a0.x, a0.y, a0.z, a0.w, a1.x, a1.y, a1.z, a1.w};
                const float bv[8] = {b0.x, b0.y, b0.z, b0.w, b1.x, b1.y, b1.z, b1.w};
                #pragma unroll
                for (int i = 0; i < 8; i++)
                    #pragma unroll
                    for (int j = 0; j < 8; j++)
                        acc[i * 8 + j] = fmaf(av[i], bv[j], acc[i * 8 + j]);
            }
        }

        if (t + 1 < T) {
            STSF(buf ^ 1);
            CP_ASYNC_WAIT_ALL();
            __syncthreads();
        }
    }

    // ------------------------------- epilogue -------------------------------
    if (wid < 8) {
        #pragma unroll
        for (int j = 0; j < 4; j++) {
            const int col = n0 + wn * 32 + j * 8 + tg * 2;
            const float2 bb = *(const float2*)(bias + col);
            #pragma unroll
            for (int i = 0; i < 4; i++) {
                const float* a4 = acc + (i * 4 + j) * 4;
                const int r0 = m0 + wm * 64 + i * 16 + g;
                float2 v0; v0.x = a4[0] + bb.x; v0.y = a4[1] + bb.y;
                *(float2*)(C + (size_t)r0 * ldc + col) = v0;
                float2 v1; v1.x = a4[2] + bb.x; v1.y = a4[3] + bb.y;
                *(float2*)(C + (size_t)(r0 + 8) * ldc + col) = v1;
            }
        }
    } else {
        const int c0 = n0 + 128 + tx * 4;
        const float4 bb0 = *(const float4*)(bias + c0);
        const float4 bb1 = *(const float4*)(bias + c0 + 64);
        #pragma unroll
        for (int i = 0; i < 8; i++) {
            const int row = m0 + ty * 8 + i;
            float* crow = C + (size_t)row * ldc;
            float4 v;
            v.x = acc[i * 8 + 0] + bb0.x; v.y = acc[i * 8 + 1] + bb0.y;
            v.z = acc[i * 8 + 2] + bb0.z; v.w = acc[i * 8 + 3] + bb0.w;
            *(float4*)(crow + c0) = v;
            v.x = acc[i * 8 + 4] + bb1.x; v.y = acc[i * 8 + 5] + bb1.y;
            v.z = acc[i * 8 + 6] + bb1.z; v.w = acc[i * 8 + 7] + bb1.w;
            *(float4*)(crow + c0 + 64) = v;
        }
    }
}

// ------------------------ fused elementwise stage ---------------------------
__device__ __forceinline__ float silu_f(float x) { return x / (1.0f + expf(-x)); }

__global__ void fused_elementwise(const float* __restrict__ xz,
                                  const float* __restrict__ h,
                                  const float* __restrict__ conv_buf,
                                  const float* __restrict__ conv_w,
                                  const float* __restrict__ conv_b,
                                  float* __restrict__ out_hnew,
                                  float* __restrict__ out_newbuf,
                                  float* __restrict__ g_out,
                                  int B, int D)
{
    const int idx = blockIdx.x * blockDim.x + threadIdx.x;
    if (idx >= B * D) return;
    const int b = idx / D;
    const int d = idx - b * D;

    const float xi = xz[(size_t)b * 2 * D + d];
    const float z  = xz[(size_t)b * 2 * D + D + d];

    const float4 cb = *(const float4*)(conv_buf + (size_t)idx * 4);
    const float4 cw = *(const float4*)(conv_w + (size_t)d * 4);

    float co = cb.y * cw.x + cb.z * cw.y + cb.w * cw.z + xi * cw.w + conv_b[d];
    co = silu_f(co);

    const float lmin = 2.302585092994046f;   // log(10)
    const float lmax = 7.600902459542082f;   // log(2000)
    const float t = lmin + (float)d * (lmax - lmin) / (float)(D - 1);
    const float dec = expf(-expf(-t));

    const float hn = dec * h[idx] + (1.0f - dec) * co;

    out_hnew[idx] = hn;
    float4 nb; nb.x = cb.y; nb.y = cb.z; nb.z = cb.w; nb.w = xi;
    *(float4*)(out_newbuf + (size_t)idx * 4) = nb;

    g_out[idx] = hn * silu_f(z);
}

// ------------------------------- launch ------------------------------------
extern "C" void kernel_launch(void* const* d_in, const int* in_sizes, int n_in,
                              void* d_out, int out_size)
{
    const float* x        = (const float*)d_in[0];
    const float* h        = (const float*)d_in[1];
    const float* conv_buf = (const float*)d_in[2];
    const float* W_in     = (const float*)d_in[3];
    const float* b_in     = (const float*)d_in[4];
    const float* conv_w   = (const float*)d_in[5];
    const float* conv_b   = (const float*)d_in[6];
    const float* W_out    = (const float*)d_in[7];
    const float* b_out    = (const float*)d_in[8];

    const int D = in_sizes[6];
    const int B = in_sizes[0] / D;
    const int twoD = in_sizes[4];

    float* out      = (float*)d_out;
    float* out_hnew = out + (size_t)B * D;
    float* out_nbuf = out + (size_t)2 * B * D;

    cudaFuncSetAttribute(gemm_hybrid,
                         cudaFuncAttributeMaxDynamicSharedMemorySize, SMEM_BYTES);

    // GEMM1: xz = x @ W_in^T + b_in   [B, 2D]
    {
        dim3 grid(twoD / BN, B / BM);
        gemm_hybrid<<<grid, NTH, SMEM_BYTES>>>(x, D, W_in, D, b_in, g_xz, twoD, D);
    }

    // fused elementwise
    {
        const int n = B * D;
        fused_elementwise<<<(n + 255) / 256, 256>>>(
            g_xz, h, conv_buf, conv_w, conv_b, out_hnew, out_nbuf, g_g, B, D);
    }

    // GEMM2: out = g @ W_out^T + b_out  [B, D]
    {
        dim3 grid(D / BN, B / BM);
        gemm_hybrid<<<grid, NTH, SMEM_BYTES>>>(g_g, D, W_out, D, b_out, out, D, D);
    }
}

// round 9
// speedup vs baseline: 1.8878x; 1.0531x over previous
#include <cuda_runtime.h>
#include <math.h>
#include <stdint.h>

// ===========================================================================
// StreamingSSMCell (B=8192, D=1024, DCONV=4) — CTA-level hybrid GEMM
//   Even CTA-groups (bid>>2 even): tf32 mma.sync + ldmatrix, N-cols [0, N/2)
//   Odd  CTA-groups:               fp32 FFMA SIMT,          N-cols [N/2, N)
//   148%4 != 0 => co-resident CTAs on one SM have opposite flavors:
//   tensor pipe (26.9 TF/s solo) + fma pipe (28.4 TF/s solo) run concurrently.
//   d_out layout: [ out (B*D) | h_new (B*D) | new_buf (B*D*4) ]
// ===========================================================================

#define D_MODEL 1024
#define TWO_D   2048
#define BATCH   8192

__device__ float g_xz[(size_t)BATCH * TWO_D];
__device__ float g_g [(size_t)BATCH * D_MODEL];

// ------------------------------ config -------------------------------------
#define BM 128
// tensor flavor: BN=128, BK=16, rows padded to 20 floats (80 B)
#define KPAD_T 20
#define ATILE_B (BM * KPAD_T * 4)          // 10240 B per operand tile
#define STAGE_B (2 * ATILE_B)              // 20480 B
#define NSTAGE  3
#define DYN_SMEM (NSTAGE * STAGE_B)        // 61440 B  (fma flavor uses 16 KB)
// fma flavor: BN=128, BK=16, As/Bs [16][128] single buffer (R1-proven)

// ------------------------------ PTX helpers --------------------------------
__device__ __forceinline__ uint32_t smem_u32(const void* p) {
    uint32_t a;
    asm("{ .reg .u64 t; cvta.to.shared.u64 t, %1; cvt.u32.u64 %0, t; }"
        : "=r"(a) : "l"(p));
    return a;
}

#define CP_ASYNC16(dst, src) \
    asm volatile("cp.async.cg.shared.global [%0], [%1], 16;" :: "r"(dst), "l"(src))
#define CP_ASYNC_COMMIT() asm volatile("cp.async.commit_group;" ::: "memory")
#define CP_ASYNC_WAIT1()  asm volatile("cp.async.wait_group 1;" ::: "memory")

__device__ __forceinline__ uint32_t rna(uint32_t x) {
    uint32_t r;
    asm("cvt.rna.tf32.f32 %0, %1;" : "=r"(r) : "f"(__uint_as_float(x)));
    return r;
}

#define LDSM_X4(r0, r1, r2, r3, addr)                                          \
    asm volatile("ldmatrix.sync.aligned.m8n8.x4.shared.b16 {%0,%1,%2,%3}, [%4];" \
        : "=r"(r0), "=r"(r1), "=r"(r2), "=r"(r3) : "r"(addr))

#define MMA_TF32(c, a, b)                                                      \
    asm volatile("mma.sync.aligned.m16n8k8.row.col.f32.tf32.tf32.f32 "         \
        "{%0,%1,%2,%3}, {%4,%5,%6,%7}, {%8,%9}, {%0,%1,%2,%3};"                \
        : "+f"((c)[0]), "+f"((c)[1]), "+f"((c)[2]), "+f"((c)[3])               \
        : "r"((a)[0]), "r"((a)[1]), "r"((a)[2]), "r"((a)[3]),                  \
          "r"((b)[0]), "r"((b)[1]))

// ----------------------------- dual GEMM ------------------------------------
// C[m,n] = sum_k A[m,k]*Bm[n,k] + bias[n]; A [M,K] lda, Bm [N,K] ldb (K-major)
// 1D grid = ntM * ntN CTAs (ntN even), halfN = ntN/2 passed in.
__global__ __launch_bounds__(256, 2)
void gemm_dual(const float* __restrict__ A, int lda,
               const float* __restrict__ Bm, int ldb,
               const float* __restrict__ bias,
               float* __restrict__ C, int ldc, int K, int halfN)
{
    extern __shared__ float smem[];
    const int tid  = threadIdx.x;
    const int bid  = blockIdx.x;
    const int group  = bid >> 2;
    const int flavor = group & 1;                     // 0 = tensor, 1 = fma
    const int rank   = (group >> 1) * 4 + (bid & 3);  // rank within flavor
    const int tm = rank / halfN;
    const int tn = rank - tm * halfN;
    const int m0 = tm * BM;
    const int n0 = (flavor ? (halfN + tn) : tn) * 128;

    float acc[64];
    #pragma unroll
    for (int i = 0; i < 64; i++) acc[i] = 0.0f;

    if (flavor == 0) {
        // ================= tensor flavor: tf32 mma.sync =================
        const uint32_t sbase = smem_u32(smem);
        const int lane = tid & 31;
        const int wid  = tid >> 5;
        const int wm = wid >> 2;          // 0..1
        const int wn = wid & 3;           // 0..3
        const int g  = lane >> 2;
        const int tg = lane & 3;

        uint32_t a_boff[4], b_boff[2];
        #pragma unroll
        for (int i = 0; i < 4; i++) {
            const int row = wm * 64 + i * 16 + (lane & 15);
            a_boff[i] = (uint32_t)(row * 80 + ((lane >> 4) * 16));
        }
        #pragma unroll
        for (int j = 0; j < 2; j++) {
            const int row = wn * 32 + j * 16 + ((lane >> 4) << 3) + (lane & 7);
            b_boff[j] = (uint32_t)(ATILE_B + row * 80 + (((lane >> 3) & 1) * 16));
        }

        // loader: 2 chunks each for A and B per thread
        const int lr = tid >> 2;          // 0..63 -> rows lr, lr+64... no:
        // chunks: id = tid + q*256; row = id>>2 (0..127), c = id&3
        const int T = K / 16;

        #define TLOAD(t) do {                                                  \
            const uint32_t _s = sbase + ((t) % NSTAGE) * STAGE_B;              \
            _Pragma("unroll")                                                  \
            for (int _q = 0; _q < 2; _q++) {                                   \
                const int _id = tid + _q * 256;                                \
                const int _r = _id >> 2, _c = _id & 3;                         \
                CP_ASYNC16(_s + (uint32_t)(_r * 80 + _c * 16),                 \
                           A + (size_t)(m0 + _r) * lda + (size_t)(t) * 16 + _c * 4); \
                CP_ASYNC16(_s + (uint32_t)(ATILE_B + _r * 80 + _c * 16),       \
                           Bm + (size_t)(n0 + _r) * ldb + (size_t)(t) * 16 + _c * 4); \
            }                                                                  \
            CP_ASYNC_COMMIT();                                                 \
        } while (0)

        TLOAD(0);
        TLOAD(1);

        for (int t = 0; t < T; t++) {
            CP_ASYNC_WAIT1();
            __syncthreads();

            if (t + 2 < T) { TLOAD(t + 2); } else { CP_ASYNC_COMMIT(); }

            const uint32_t st = sbase + (t % NSTAGE) * STAGE_B;

            #pragma unroll
            for (int ks = 0; ks < 2; ks++) {
                const uint32_t kb = (uint32_t)(ks * 32);
                uint32_t af[4][4], bf[4][2];
                #pragma unroll
                for (int i = 0; i < 4; i++)
                    LDSM_X4(af[i][0], af[i][1], af[i][2], af[i][3],
                            st + a_boff[i] + kb);
                #pragma unroll
                for (int j = 0; j < 2; j++)
                    LDSM_X4(bf[2 * j][0], bf[2 * j][1],
                            bf[2 * j + 1][0], bf[2 * j + 1][1],
                            st + b_boff[j] + kb);
                #pragma unroll
                for (int i = 0; i < 4; i++)
                    #pragma unroll
                    for (int q = 0; q < 4; q++) af[i][q] = rna(af[i][q]);
                #pragma unroll
                for (int j = 0; j < 4; j++) {
                    bf[j][0] = rna(bf[j][0]);
                    bf[j][1] = rna(bf[j][1]);
                }
                #pragma unroll
                for (int i = 0; i < 4; i++)
                    #pragma unroll
                    for (int j = 0; j < 4; j++)
                        MMA_TF32((acc + (i * 4 + j) * 4), af[i], bf[j]);
            }
        }
        #undef TLOAD

        // epilogue
        #pragma unroll
        for (int j = 0; j < 4; j++) {
            const int col = n0 + wn * 32 + j * 8 + tg * 2;
            const float2 bb = *(const float2*)(bias + col);
            #pragma unroll
            for (int i = 0; i < 4; i++) {
                const float* a4 = acc + (i * 4 + j) * 4;
                const int r0 = m0 + wm * 64 + i * 16 + g;
                float2 v0; v0.x = a4[0] + bb.x; v0.y = a4[1] + bb.y;
                *(float2*)(C + (size_t)r0 * ldc + col) = v0;
                float2 v1; v1.x = a4[2] + bb.x; v1.y = a4[3] + bb.y;
                *(float2*)(C + (size_t)(r0 + 8) * ldc + col) = v1;
            }
        }
    } else {
        // ================= fma flavor: fp32 SIMT (R1-proven) =================
        float* As = smem;                       // [16][128]
        float* Bs = smem + 16 * 128;            // [16][128]

        const int tx = tid & 15;
        const int ty = tid >> 4;
        const int lrow = tid >> 2;              // 0..63
        const int lcol = (tid & 3) * 4;         // 0,4,8,12

        for (int k0 = 0; k0 < K; k0 += 16) {
            float4 va0 = *(const float4*)(A + (size_t)(m0 + lrow) * lda + k0 + lcol);
            float4 va1 = *(const float4*)(A + (size_t)(m0 + lrow + 64) * lda + k0 + lcol);
            float4 vb0 = *(const float4*)(Bm + (size_t)(n0 + lrow) * ldb + k0 + lcol);
            float4 vb1 = *(const float4*)(Bm + (size_t)(n0 + lrow + 64) * ldb + k0 + lcol);

            #pragma unroll
            for (int j = 0; j < 4; j++) {
                As[(lcol + j) * 128 + lrow]      = ((const float*)&va0)[j];
                As[(lcol + j) * 128 + lrow + 64] = ((const float*)&va1)[j];
                Bs[(lcol + j) * 128 + lrow]      = ((const float*)&vb0)[j];
                Bs[(lcol + j) * 128 + lrow + 64] = ((const float*)&vb1)[j];
            }
            __syncthreads();

            #pragma unroll
            for (int k = 0; k < 16; k++) {
                float4 a0 = *(const float4*)&As[k * 128 + ty * 8];
                float4 a1 = *(const float4*)&As[k * 128 + ty * 8 + 4];
                float4 b0 = *(const float4*)&Bs[k * 128 + tx * 8];
                float4 b1 = *(const float4*)&Bs[k * 128 + tx * 8 + 4];
                const float ra[8] = {a0.x, a0.y, a0.z, a0.w, a1.x, a1.y, a1.z, a1.w};
                const float rb[8] = {b0.x, b0.y, b0.z, b0.w, b1.x, b1.y, b1.z, b1.w};
                #pragma unroll
                for (int i = 0; i < 8; i++)
                    #pragma unroll
                    for (int j = 0; j < 8; j++)
                        acc[i * 8 + j] = fmaf(ra[i], rb[j], acc[i * 8 + j]);
            }
            __syncthreads();
        }

        // epilogue
        #pragma unroll
        for (int i = 0; i < 8; i++) {
            const int row = m0 + ty * 8 + i;
            #pragma unroll
            for (int j = 0; j < 8; j += 4) {
                const int col = n0 + tx * 8 + j;
                const float4 bb = *(const float4*)(bias + col);
                float4 v;
                v.x = acc[i * 8 + j + 0] + bb.x;
                v.y = acc[i * 8 + j + 1] + bb.y;
                v.z = acc[i * 8 + j + 2] + bb.z;
                v.w = acc[i * 8 + j + 3] + bb.w;
                *(float4*)(C + (size_t)row * ldc + col) = v;
            }
        }
    }
}

// ------------------------ fused elementwise stage ---------------------------
__device__ __forceinline__ float silu_f(float x) { return x / (1.0f + expf(-x)); }

__global__ void fused_elementwise(const float* __restrict__ xz,
                                  const float* __restrict__ h,
                                  const float* __restrict__ conv_buf,
                                  const float* __restrict__ conv_w,
                                  const float* __restrict__ conv_b,
                                  float* __restrict__ out_hnew,
                                  float* __restrict__ out_newbuf,
                                  float* __restrict__ g_out,
                                  int B, int D)
{
    const int idx = blockIdx.x * blockDim.x + threadIdx.x;
    if (idx >= B * D) return;
    const int b = idx / D;
    const int d = idx - b * D;

    const float xi = xz[(size_t)b * 2 * D + d];
    const float z  = xz[(size_t)b * 2 * D + D + d];

    const float4 cb = *(const float4*)(conv_buf + (size_t)idx * 4);
    const float4 cw = *(const float4*)(conv_w + (size_t)d * 4);

    float co = cb.y * cw.x + cb.z * cw.y + cb.w * cw.z + xi * cw.w + conv_b[d];
    co = silu_f(co);

    const float lmin = 2.302585092994046f;   // log(10)
    const float lmax = 7.600902459542082f;   // log(2000)
    const float t = lmin + (float)d * (lmax - lmin) / (float)(D - 1);
    const float dec = expf(-expf(-t));

    const float hn = dec * h[idx] + (1.0f - dec) * co;

    out_hnew[idx] = hn;
    float4 nb; nb.x = cb.y; nb.y = cb.z; nb.z = cb.w; nb.w = xi;
    *(float4*)(out_newbuf + (size_t)idx * 4) = nb;

    g_out[idx] = hn * silu_f(z);
}

// ------------------------------- launch ------------------------------------
extern "C" void kernel_launch(void* const* d_in, const int* in_sizes, int n_in,
                              void* d_out, int out_size)
{
    const float* x        = (const float*)d_in[0];
    const float* h        = (const float*)d_in[1];
    const float* conv_buf = (const float*)d_in[2];
    const float* W_in     = (const float*)d_in[3];
    const float* b_in     = (const float*)d_in[4];
    const float* conv_w   = (const float*)d_in[5];
    const float* conv_b   = (const float*)d_in[6];
    const float* W_out    = (const float*)d_in[7];
    const float* b_out    = (const float*)d_in[8];

    const int D = in_sizes[6];
    const int B = in_sizes[0] / D;
    const int twoD = in_sizes[4];

    float* out      = (float*)d_out;
    float* out_hnew = out + (size_t)B * D;
    float* out_nbuf = out + (size_t)2 * B * D;

    cudaFuncSetAttribute(gemm_dual,
                         cudaFuncAttributeMaxDynamicSharedMemorySize, DYN_SMEM);

    // GEMM1: xz = x @ W_in^T + b_in   [B, 2D]  (64 x 16 tiles, halfN = 8)
    {
        const int grid = (B / BM) * (twoD / 128);
        gemm_dual<<<grid, 256, DYN_SMEM>>>(x, D, W_in, D, b_in, g_xz, twoD, D,
                                           (twoD / 128) / 2);
    }

    // fused elementwise
    {
        const int n = B * D;
        fused_elementwise<<<(n + 255) / 256, 256>>>(
            g_xz, h, conv_buf, conv_w, conv_b, out_hnew, out_nbuf, g_g, B, D);
    }

    // GEMM2: out = g @ W_out^T + b_out  [B, D]  (64 x 8 tiles, halfN = 4)
    {
        const int grid = (B / BM) * (D / 128);
        gemm_dual<<<grid, 256, DYN_SMEM>>>(g_g, D, W_out, D, b_out, out, D, D,
                                           (D / 128) / 2);
    }
}

// round 10
// speedup vs baseline: 1.9268x; 1.0207x over previous
#include <cuda_runtime.h>
#include <math.h>
#include <stdint.h>

// ===========================================================================
// StreamingSSMCell (B=8192, D=1024, DCONV=4) — persistent dual-flavor GEMM
//   grid = 296 = 2 x 148: bid<148 -> tensor flavor (tf32 mma, cols [0,N/2))
//                         bid>=148 -> fma flavor (fp32 FFMA, cols [N/2,N))
//   Classic placement maps bid and bid+148 to the SAME SM -> every SM runs
//   one tensor CTA + one fma CTA concurrently, persistent over tiles.
//   d_out layout: [ out (B*D) | h_new (B*D) | new_buf (B*D*4) ]
// ===========================================================================

#define D_MODEL 1024
#define TWO_D   2048
#define BATCH   8192
#define NSM     148

__device__ float g_xz[(size_t)BATCH * TWO_D];
__device__ float g_g [(size_t)BATCH * D_MODEL];

// ------------------------------ config -------------------------------------
// tensor flavor: 128x128 tile, BK=16, rows padded to 80 B, 3-stage cp.async
#define ATILE_B (128 * 80)                 // 10240 B per operand tile
#define STAGE_B (2 * ATILE_B)              // 20480 B
#define NSTAGE  3
#define DYN_SMEM (NSTAGE * STAGE_B)        // 61440 B (fma flavor uses 16 KB)

// ------------------------------ PTX helpers --------------------------------
__device__ __forceinline__ uint32_t smem_u32(const void* p) {
    uint32_t a;
    asm("{ .reg .u64 t; cvta.to.shared.u64 t, %1; cvt.u32.u64 %0, t; }"
        : "=r"(a) : "l"(p));
    return a;
}

#define CP_ASYNC16(dst, src) \
    asm volatile("cp.async.cg.shared.global [%0], [%1], 16;" :: "r"(dst), "l"(src))
#define CP_ASYNC_COMMIT()   asm volatile("cp.async.commit_group;" ::: "memory")
#define CP_ASYNC_WAIT1()    asm volatile("cp.async.wait_group 1;" ::: "memory")
#define CP_ASYNC_WAIT_ALL() asm volatile("cp.async.wait_group 0;" ::: "memory")

__device__ __forceinline__ uint32_t rna(uint32_t x) {
    uint32_t r;
    asm("cvt.rna.tf32.f32 %0, %1;" : "=r"(r) : "f"(__uint_as_float(x)));
    return r;
}

#define LDSM_X4(r0, r1, r2, r3, addr)                                          \
    asm volatile("ldmatrix.sync.aligned.m8n8.x4.shared.b16 {%0,%1,%2,%3}, [%4];" \
        : "=r"(r0), "=r"(r1), "=r"(r2), "=r"(r3) : "r"(addr))

#define MMA_TF32(c, a, b)                                                      \
    asm volatile("mma.sync.aligned.m16n8k8.row.col.f32.tf32.tf32.f32 "         \
        "{%0,%1,%2,%3}, {%4,%5,%6,%7}, {%8,%9}, {%0,%1,%2,%3};"                \
        : "+f"((c)[0]), "+f"((c)[1]), "+f"((c)[2]), "+f"((c)[3])               \
        : "r"((a)[0]), "r"((a)[1]), "r"((a)[2]), "r"((a)[3]),                  \
          "r"((b)[0]), "r"((b)[1]))

// ----------------------------- dual GEMM ------------------------------------
// C[m,n] = sum_k A[m,k]*Bm[n,k] + bias[n]; A [M,K] lda, Bm [N,K] ldb (K-major)
// grid = 296 persistent CTAs; tiles are 128x128; nHalf = (N/128)/2.
__global__ __launch_bounds__(256, 2)
void gemm_dual(const float* __restrict__ A, int lda,
               const float* __restrict__ Bm, int ldb,
               const float* __restrict__ bias,
               float* __restrict__ C, int ldc, int K,
               int mTiles, int nHalf)
{
    extern __shared__ float smem[];
    const int tid = threadIdx.x;
    const int bid = blockIdx.x;
    const int flavor = (bid >= NSM) ? 1 : 0;
    const int rank   = flavor ? (bid - NSM) : bid;
    const int nTiles = mTiles * nHalf;

    if (flavor == 0) {
        // ================= tensor flavor: tf32 mma.sync =================
        const uint32_t sbase = smem_u32(smem);
        const int lane = tid & 31;
        const int wid  = tid >> 5;
        const int wm = wid >> 2;          // 0..1
        const int wn = wid & 3;           // 0..3
        const int g  = lane >> 2;
        const int tg = lane & 3;

        uint32_t a_boff[4], b_boff[2];
        #pragma unroll
        for (int i = 0; i < 4; i++) {
            const int row = wm * 64 + i * 16 + (lane & 15);
            a_boff[i] = (uint32_t)(row * 80 + ((lane >> 4) * 16));
        }
        #pragma unroll
        for (int j = 0; j < 2; j++) {
            const int row = wn * 32 + j * 16 + ((lane >> 4) << 3) + (lane & 7);
            b_boff[j] = (uint32_t)(ATILE_B + row * 80 + (((lane >> 3) & 1) * 16));
        }

        const int T = K / 16;

        for (int tile = rank; tile < nTiles; tile += NSM) {
            const int tm = tile / nHalf;
            const int tn = tile - tm * nHalf;
            const int m0 = tm * 128;
            const int n0 = tn * 128;

            float acc[64];
            #pragma unroll
            for (int i = 0; i < 64; i++) acc[i] = 0.0f;

            CP_ASYNC_WAIT_ALL();
            __syncthreads();            // smem safe to overwrite across tiles

            #define TLOAD(t) do {                                              \
                const uint32_t _s = sbase + ((t) % NSTAGE) * STAGE_B;          \
                _Pragma("unroll")                                              \
                for (int _q = 0; _q < 2; _q++) {                               \
                    const int _id = tid + _q * 256;                            \
                    const int _r = _id >> 2, _c = _id & 3;                     \
                    CP_ASYNC16(_s + (uint32_t)(_r * 80 + _c * 16),             \
                               A + (size_t)(m0 + _r) * lda + (size_t)(t) * 16 + _c * 4); \
                    CP_ASYNC16(_s + (uint32_t)(ATILE_B + _r * 80 + _c * 16),   \
                               Bm + (size_t)(n0 + _r) * ldb + (size_t)(t) * 16 + _c * 4); \
                }                                                              \
                CP_ASYNC_COMMIT();                                             \
            } while (0)

            TLOAD(0);
            TLOAD(1);

            for (int t = 0; t < T; t++) {
                CP_ASYNC_WAIT1();
                __syncthreads();

                if (t + 2 < T) { TLOAD(t + 2); } else { CP_ASYNC_COMMIT(); }

                const uint32_t st = sbase + (t % NSTAGE) * STAGE_B;

                #pragma unroll
                for (int ks = 0; ks < 2; ks++) {
                    const uint32_t kb = (uint32_t)(ks * 32);
                    uint32_t af[4][4], bf[4][2];
                    #pragma unroll
                    for (int i = 0; i < 4; i++)
                        LDSM_X4(af[i][0], af[i][1], af[i][2], af[i][3],
                                st + a_boff[i] + kb);
                    #pragma unroll
                    for (int j = 0; j < 2; j++)
                        LDSM_X4(bf[2 * j][0], bf[2 * j][1],
                                bf[2 * j + 1][0], bf[2 * j + 1][1],
                                st + b_boff[j] + kb);
                    #pragma unroll
                    for (int i = 0; i < 4; i++)
                        #pragma unroll
                        for (int q = 0; q < 4; q++) af[i][q] = rna(af[i][q]);
                    #pragma unroll
                    for (int j = 0; j < 4; j++) {
                        bf[j][0] = rna(bf[j][0]);
                        bf[j][1] = rna(bf[j][1]);
                    }
                    #pragma unroll
                    for (int i = 0; i < 4; i++)
                        #pragma unroll
                        for (int j = 0; j < 4; j++)
                            MMA_TF32((acc + (i * 4 + j) * 4), af[i], bf[j]);
                }
            }
            #undef TLOAD

            // epilogue
            #pragma unroll
            for (int j = 0; j < 4; j++) {
                const int col = n0 + wn * 32 + j * 8 + tg * 2;
                const float2 bb = *(const float2*)(bias + col);
                #pragma unroll
                for (int i = 0; i < 4; i++) {
                    const float* a4 = acc + (i * 4 + j) * 4;
                    const int r0 = m0 + wm * 64 + i * 16 + g;
                    float2 v0; v0.x = a4[0] + bb.x; v0.y = a4[1] + bb.y;
                    *(float2*)(C + (size_t)r0 * ldc + col) = v0;
                    float2 v1; v1.x = a4[2] + bb.x; v1.y = a4[3] + bb.y;
                    *(float2*)(C + (size_t)(r0 + 8) * ldc + col) = v1;
                }
            }
        }
    } else {
        // ============ fma flavor: fp32 SIMT, conflict-free B reads ============
        float* As = smem;                       // [16][128]
        float* Bs = smem + 16 * 128;            // [16][128]

        const int tx = tid & 15;                // cols tx*4 and 64+tx*4
        const int ty = tid >> 4;                // rows ty*8..+7
        const int lrow = tid >> 2;              // 0..63
        const int lcol = (tid & 3) * 4;         // 0,4,8,12

        for (int tile = rank; tile < nTiles; tile += NSM) {
            const int tm = tile / nHalf;
            const int tn = tile - tm * nHalf;
            const int m0 = tm * 128;
            const int n0 = (nHalf + tn) * 128;

            float acc[64];
            #pragma unroll
            for (int i = 0; i < 64; i++) acc[i] = 0.0f;

            __syncthreads();                     // tile boundary

            for (int k0 = 0; k0 < K; k0 += 16) {
                float4 va0 = *(const float4*)(A + (size_t)(m0 + lrow) * lda + k0 + lcol);
                float4 va1 = *(const float4*)(A + (size_t)(m0 + lrow + 64) * lda + k0 + lcol);
                float4 vb0 = *(const float4*)(Bm + (size_t)(n0 + lrow) * ldb + k0 + lcol);
                float4 vb1 = *(const float4*)(Bm + (size_t)(n0 + lrow + 64) * ldb + k0 + lcol);

                #pragma unroll
                for (int j = 0; j < 4; j++) {
                    As[(lcol + j) * 128 + lrow]      = ((const float*)&va0)[j];
                    As[(lcol + j) * 128 + lrow + 64] = ((const float*)&va1)[j];
                    Bs[(lcol + j) * 128 + lrow]      = ((const float*)&vb0)[j];
                    Bs[(lcol + j) * 128 + lrow + 64] = ((const float*)&vb1)[j];
                }
                __syncthreads();

                #pragma unroll
                for (int k = 0; k < 16; k++) {
                    float4 a0 = *(const float4*)&As[k * 128 + ty * 8];
                    float4 a1 = *(const float4*)&As[k * 128 + ty * 8 + 4];
                    float4 b0 = *(const float4*)&Bs[k * 128 + tx * 4];       // CF
                    float4 b1 = *(const float4*)&Bs[k * 128 + 64 + tx * 4];  // CF
                    const float ra[8] = {a0.x, a0.y, a0.z, a0.w, a1.x, a1.y, a1.z, a1.w};
                    const float rb[8] = {b0.x, b0.y, b0.z, b0.w, b1.x, b1.y, b1.z, b1.w};
                    #pragma unroll
                    for (int i = 0; i < 8; i++)
                        #pragma unroll
                        for (int j = 0; j < 8; j++)
                            acc[i * 8 + j] = fmaf(ra[i], rb[j], acc[i * 8 + j]);
                }
                __syncthreads();
            }

            // epilogue: cols {n0+tx*4, n0+64+tx*4}
            const int c0 = n0 + tx * 4;
            const float4 bb0 = *(const float4*)(bias + c0);
            const float4 bb1 = *(const float4*)(bias + c0 + 64);
            #pragma unroll
            for (int i = 0; i < 8; i++) {
                const int row = m0 + ty * 8 + i;
                float* crow = C + (size_t)row * ldc;
                float4 v;
                v.x = acc[i * 8 + 0] + bb0.x; v.y = acc[i * 8 + 1] + bb0.y;
                v.z = acc[i * 8 + 2] + bb0.z; v.w = acc[i * 8 + 3] + bb0.w;
                *(float4*)(crow + c0) = v;
                v.x = acc[i * 8 + 4] + bb1.x; v.y = acc[i * 8 + 5] + bb1.y;
                v.z = acc[i * 8 + 6] + bb1.z; v.w = acc[i * 8 + 7] + bb1.w;
                *(float4*)(crow + c0 + 64) = v;
            }
        }
    }
}

// ------------------------ fused elementwise stage ---------------------------
__device__ __forceinline__ float silu_f(float x) { return x / (1.0f + expf(-x)); }

__global__ void fused_elementwise(const float* __restrict__ xz,
                                  const float* __restrict__ h,
                                  const float* __restrict__ conv_buf,
                                  const float* __restrict__ conv_w,
                                  const float* __restrict__ conv_b,
                                  float* __restrict__ out_hnew,
                                  float* __restrict__ out_newbuf,
                                  float* __restrict__ g_out,
                                  int B, int D)
{
    const int idx = blockIdx.x * blockDim.x + threadIdx.x;
    if (idx >= B * D) return;
    const int b = idx / D;
    const int d = idx - b * D;

    const float xi = xz[(size_t)b * 2 * D + d];
    const float z  = xz[(size_t)b * 2 * D + D + d];

    const float4 cb = *(const float4*)(conv_buf + (size_t)idx * 4);
    const float4 cw = *(const float4*)(conv_w + (size_t)d * 4);

    float co = cb.y * cw.x + cb.z * cw.y + cb.w * cw.z + xi * cw.w + conv_b[d];
    co = silu_f(co);

    const float lmin = 2.302585092994046f;   // log(10)
    const float lmax = 7.600902459542082f;   // log(2000)
    const float t = lmin + (float)d * (lmax - lmin) / (float)(D - 1);
    const float dec = expf(-expf(-t));

    const float hn = dec * h[idx] + (1.0f - dec) * co;

    out_hnew[idx] = hn;
    float4 nb; nb.x = cb.y; nb.y = cb.z; nb.z = cb.w; nb.w = xi;
    *(float4*)(out_newbuf + (size_t)idx * 4) = nb;

    g_out[idx] = hn * silu_f(z);
}

// ------------------------------- launch ------------------------------------
extern "C" void kernel_launch(void* const* d_in, const int* in_sizes, int n_in,
                              void* d_out, int out_size)
{
    const float* x        = (const float*)d_in[0];
    const float* h        = (const float*)d_in[1];
    const float* conv_buf = (const float*)d_in[2];
    const float* W_in     = (const float*)d_in[3];
    const float* b_in     = (const float*)d_in[4];
    const float* conv_w   = (const float*)d_in[5];
    const float* conv_b   = (const float*)d_in[6];
    const float* W_out    = (const float*)d_in[7];
    const float* b_out    = (const float*)d_in[8];

    const int D = in_sizes[6];
    const int B = in_sizes[0] / D;
    const int twoD = in_sizes[4];

    float* out      = (float*)d_out;
    float* out_hnew = out + (size_t)B * D;
    float* out_nbuf = out + (size_t)2 * B * D;

    cudaFuncSetAttribute(gemm_dual,
                         cudaFuncAttributeMaxDynamicSharedMemorySize, DYN_SMEM);

    // GEMM1: xz = x @ W_in^T + b_in   [B, 2D]; mTiles=64, nHalf=8
    gemm_dual<<<2 * NSM, 256, DYN_SMEM>>>(x, D, W_in, D, b_in, g_xz, twoD, D,
                                          B / 128, (twoD / 128) / 2);

    // fused elementwise
    {
        const int n = B * D;
        fused_elementwise<<<(n + 255) / 256, 256>>>(
            g_xz, h, conv_buf, conv_w, conv_b, out_hnew, out_nbuf, g_g, B, D);
    }

    // GEMM2: out = g @ W_out^T + b_out  [B, D]; mTiles=64, nHalf=4
    gemm_dual<<<2 * NSM, 256, DYN_SMEM>>>(g_g, D, W_out, D, b_out, out, D, D,
                                          B / 128, (D / 128) / 2);
}

// round 11
// speedup vs baseline: 3.4578x; 1.7945x over previous
#include <cuda_runtime.h>
#include <math.h>
#include <stdint.h>

// ===========================================================================
// StreamingSSMCell (B=8192, D=1024, DCONV=4) — tf32 GEMM + FUSED epilogue
//   GEMM1 computes interleaved (x_inner, z) column pairs per CTA (W_in rows
//   interleaved in the B tile), so each thread's C-fragment holds matched
//   (x_inner[b,d], z[b,d]) pairs -> conv/decay/gate fused into the epilogue.
//   GEMM1 writes h_new, new_buf, g directly (no xz scratch, no elementwise).
//   GEMM2: out = g @ W_out^T + b_out (proven tf32 ldmatrix kernel).
//   d_out layout: [ out (B*D) | h_new (B*D) | new_buf (B*D*4) ]
// ===========================================================================

#define D_MODEL 1024
#define BATCH   8192

__device__ float g_g[(size_t)BATCH * D_MODEL];   // gated activation

// ------------------------------ GEMM config --------------------------------
#define BM 128
#define BN 256
#define BK 32
#define KPAD 36                          // 32 + 4 floats pad (row = 144B)
#define NTHREADS 512                     // 16 warps: wm(2) x wn(8), 64x32 each
#define NSTAGE 3
#define A_TILE_WORDS (BM * KPAD)
#define B_TILE_WORDS (BN * KPAD)
#define STAGE_WORDS  (A_TILE_WORDS + B_TILE_WORDS)
#define SMEM_BYTES   (NSTAGE * STAGE_WORDS * 4)      // 165888

// ------------------------------ PTX helpers --------------------------------
__device__ __forceinline__ uint32_t smem_u32(const void* p) {
    uint32_t a;
    asm("{ .reg .u64 t; cvta.to.shared.u64 t, %1; cvt.u32.u64 %0, t; }"
        : "=r"(a) : "l"(p));
    return a;
}

#define CP_ASYNC16(dst, src) \
    asm volatile("cp.async.cg.shared.global [%0], [%1], 16;" :: "r"(dst), "l"(src))
#define CP_ASYNC_COMMIT() asm volatile("cp.async.commit_group;" ::: "memory")
#define CP_ASYNC_WAIT1()  asm volatile("cp.async.wait_group 1;" ::: "memory")

__device__ __forceinline__ uint32_t rna(uint32_t x) {
    uint32_t r;
    asm("cvt.rna.tf32.f32 %0, %1;" : "=r"(r) : "f"(__uint_as_float(x)));
    return r;
}

#define LDSM_X4(r0, r1, r2, r3, addr)                                          \
    asm volatile("ldmatrix.sync.aligned.m8n8.x4.shared.b16 {%0,%1,%2,%3}, [%4];" \
        : "=r"(r0), "=r"(r1), "=r"(r2), "=r"(r3) : "r"(addr))

#define MMA_TF32(c, a, b)                                                      \
    asm volatile("mma.sync.aligned.m16n8k8.row.col.f32.tf32.tf32.f32 "         \
        "{%0,%1,%2,%3}, {%4,%5,%6,%7}, {%8,%9}, {%0,%1,%2,%3};"                \
        : "+f"((c)[0]), "+f"((c)[1]), "+f"((c)[2]), "+f"((c)[3])               \
        : "r"((a)[0]), "r"((a)[1]), "r"((a)[2]), "r"((a)[3]),                  \
          "r"((b)[0]), "r"((b)[1]))

__device__ __forceinline__ float silu_f(float x) { return x / (1.0f + expf(-x)); }

// ====================== GEMM1 + fused elementwise ===========================
// Computes xz-pairs for d in [bx*128, bx*128+128), rows [by*128, +128).
// B tile row r <- W_in row (r&1)*D + n0d + (r>>1)  (x_inner / z interleave).
// Epilogue: conv ring buffer + silu + decay + gate; writes hnew/newbuf/g.
__global__ __launch_bounds__(NTHREADS, 1)
void gemm1_fused(const float* __restrict__ A,        // x [B, D]
                 const float* __restrict__ Bm,       // W_in [2D, D]
                 const float* __restrict__ b_in,     // [2D]
                 const float* __restrict__ h,        // [B, D]
                 const float* __restrict__ conv_buf, // [B, D, 4]
                 const float* __restrict__ conv_w,   // [D, 4]
                 const float* __restrict__ conv_b,   // [D]
                 float* __restrict__ out_hnew,       // [B, D]
                 float* __restrict__ out_newbuf,     // [B, D, 4]
                 float* __restrict__ g_out)          // [B, D]
{
    extern __shared__ float smem[];
    const uint32_t sbase = smem_u32(smem);
    const int tid  = threadIdx.x;
    const int lane = tid & 31;
    const int wid  = tid >> 5;
    const int wm = wid >> 3;             // 0..1
    const int wn = wid & 7;              // 0..7
    const int g  = lane >> 2;
    const int tg = lane & 3;
    const int m0  = blockIdx.y * BM;
    const int n0d = blockIdx.x * 128;    // d-range base (128 d's -> 256 cols)
    const int K = D_MODEL;

    uint32_t a_off[4];
    #pragma unroll
    for (int i = 0; i < 4; i++) {
        const int row = wm * 64 + i * 16 + (lane & 15);
        a_off[i] = (uint32_t)(row * KPAD + ((lane >> 4) << 2)) * 4u;
    }
    uint32_t b_off[2];
    #pragma unroll
    for (int jj = 0; jj < 2; jj++) {
        const int row = wn * 32 + jj * 16 + ((lane >> 4) << 3) + (lane & 7);
        b_off[jj] = (uint32_t)(row * KPAD + (((lane >> 3) & 1) << 2)) * 4u
                    + (uint32_t)(A_TILE_WORDS * 4);
    }

    float acc[4][4][4];
    #pragma unroll
    for (int i = 0; i < 4; i++)
        #pragma unroll
        for (int j = 0; j < 4; j++)
            #pragma unroll
            for (int r = 0; r < 4; r++) acc[i][j][r] = 0.0f;

    const int T = K / BK;

    #define LOAD_STAGE1(t) do {                                                \
        const uint32_t _s = sbase + ((t) % NSTAGE) * (STAGE_WORDS * 4);        \
        _Pragma("unroll")                                                      \
        for (int _q = 0; _q < 2; _q++) {                                       \
            const int _id = tid + _q * NTHREADS;                               \
            const int _r = _id >> 3, _c = _id & 7;                             \
            CP_ASYNC16(_s + _r * (KPAD * 4) + _c * 16,                         \
                       A + (size_t)(m0 + _r) * D_MODEL + (size_t)(t) * BK + _c * 4); \
        }                                                                      \
        const uint32_t _sb = _s + A_TILE_WORDS * 4;                            \
        _Pragma("unroll")                                                      \
        for (int _q = 0; _q < 4; _q++) {                                       \
            const int _id = tid + _q * NTHREADS;                               \
            const int _r = _id >> 3, _c = _id & 7;                             \
            const int _grow = ((_id & 8) ? D_MODEL : 0) + n0d + (_r >> 1);     \
            CP_ASYNC16(_sb + _r * (KPAD * 4) + _c * 16,                        \
                       Bm + (size_t)_grow * D_MODEL + (size_t)(t) * BK + _c * 4); \
        }                                                                      \
        CP_ASYNC_COMMIT();                                                     \
    } while (0)
    // note: _r&1 == (_id>>3)&1 == (_id&8)>>3

    LOAD_STAGE1(0);
    LOAD_STAGE1(1);

    for (int t = 0; t < T; t++) {
        CP_ASYNC_WAIT1();
        __syncthreads();

        if (t + 2 < T) { LOAD_STAGE1(t + 2); } else { CP_ASYNC_COMMIT(); }

        const uint32_t st = sbase + (t % NSTAGE) * (STAGE_WORDS * 4);

        #pragma unroll
        for (int k0 = 0; k0 < BK; k0 += 8) {
            const uint32_t kb = (uint32_t)(k0 * 4);
            uint32_t af[4][4], bf[4][2];
            #pragma unroll
            for (int i = 0; i < 4; i++)
                LDSM_X4(af[i][0], af[i][1], af[i][2], af[i][3],
                        st + a_off[i] + kb);
            #pragma unroll
            for (int jj = 0; jj < 2; jj++)
                LDSM_X4(bf[jj * 2][0], bf[jj * 2][1],
                        bf[jj * 2 + 1][0], bf[jj * 2 + 1][1],
                        st + b_off[jj] + kb);
            #pragma unroll
            for (int i = 0; i < 4; i++)
                #pragma unroll
                for (int q = 0; q < 4; q++) af[i][q] = rna(af[i][q]);
            #pragma unroll
            for (int j = 0; j < 4; j++) {
                bf[j][0] = rna(bf[j][0]);
                bf[j][1] = rna(bf[j][1]);
            }
            #pragma unroll
            for (int i = 0; i < 4; i++)
                #pragma unroll
                for (int j = 0; j < 4; j++)
                    MMA_TF32(acc[i][j], af[i], bf[j]);
        }
    }
    #undef LOAD_STAGE1

    // ---------------- fused elementwise epilogue ----------------
    // fragment (i,j): cols (even, odd) = (x_inner, z) for d = n0d + wn*16+j*4+tg
    //                 rows m0+wm*64+i*16+g (regs 0,1) and +8 (regs 2,3)
    #pragma unroll
    for (int j = 0; j < 4; j++) {
        const int d = n0d + wn * 16 + j * 4 + tg;
        const float bi  = b_in[d];
        const float biz = b_in[D_MODEL + d];
        const float4 cw = *(const float4*)(conv_w + (size_t)d * 4);
        const float cbv = conv_b[d];
        // decay[d] = exp(-exp(-t)), t = log(10) + d*(log(2000)-log(10))/(D-1)
        const float tt = 2.302585092994046f
                       + (float)d * (7.600902459542082f - 2.302585092994046f)
                         / (float)(D_MODEL - 1);
        const float dec = expf(-expf(-tt));

        #pragma unroll
        for (int i = 0; i < 4; i++) {
            #pragma unroll
            for (int e = 0; e < 2; e++) {
                const int row = m0 + wm * 64 + i * 16 + g + e * 8;
                const size_t idx = (size_t)row * D_MODEL + d;

                const float xi = acc[i][j][e * 2 + 0] + bi;
                const float zz = acc[i][j][e * 2 + 1] + biz;

                const float4 cb = *(const float4*)(conv_buf + idx * 4);
                float co = cb.y * cw.x + cb.z * cw.y + cb.w * cw.z
                         + xi * cw.w + cbv;
                co = silu_f(co);

                const float hn = dec * h[idx] + (1.0f - dec) * co;

                out_hnew[idx] = hn;
                float4 nb; nb.x = cb.y; nb.y = cb.z; nb.z = cb.w; nb.w = xi;
                *(float4*)(out_newbuf + idx * 4) = nb;
                g_out[idx] = hn * silu_f(zz);
            }
        }
    }
}

// ========================= GEMM2 (proven tf32) ==============================
// C[m,n] = sum_k A[m,k]*Bm[n,k] + bias[n]
__global__ __launch_bounds__(NTHREADS, 1)
void gemm_tf32(const float* __restrict__ A, int lda,
               const float* __restrict__ Bm, int ldb,
               const float* __restrict__ bias,
               float* __restrict__ C, int ldc, int K)
{
    extern __shared__ float smem[];
    const uint32_t sbase = smem_u32(smem);
    const int tid  = threadIdx.x;
    const int lane = tid & 31;
    const int wid  = tid >> 5;
    const int wm = wid >> 3;
    const int wn = wid & 7;
    const int g  = lane >> 2;
    const int tg = lane & 3;
    const int m0 = blockIdx.y * BM;
    const int n0 = blockIdx.x * BN;

    const float* gA = A  + (size_t)m0 * lda;
    const float* gB = Bm + (size_t)n0 * ldb;

    uint32_t a_off[4];
    #pragma unroll
    for (int i = 0; i < 4; i++) {
        const int row = wm * 64 + i * 16 + (lane & 15);
        a_off[i] = (uint32_t)(row * KPAD + ((lane >> 4) << 2)) * 4u;
    }
    uint32_t b_off[2];
    #pragma unroll
    for (int jj = 0; jj < 2; jj++) {
        const int row = wn * 32 + jj * 16 + ((lane >> 4) << 3) + (lane & 7);
        b_off[jj] = (uint32_t)(row * KPAD + (((lane >> 3) & 1) << 2)) * 4u
                    + (uint32_t)(A_TILE_WORDS * 4);
    }

    float acc[4][4][4];
    #pragma unroll
    for (int i = 0; i < 4; i++)
        #pragma unroll
        for (int j = 0; j < 4; j++)
            #pragma unroll
            for (int r = 0; r < 4; r++) acc[i][j][r] = 0.0f;

    const int T = K / BK;

    #define LOAD_STAGE(t) do {                                                 \
        const uint32_t _s = sbase + ((t) % NSTAGE) * (STAGE_WORDS * 4);        \
        _Pragma("unroll")                                                      \
        for (int _q = 0; _q < 2; _q++) {                                       \
            const int _id = tid + _q * NTHREADS;                               \
            const int _r = _id >> 3, _c = _id & 7;                             \
            CP_ASYNC16(_s + _r * (KPAD * 4) + _c * 16,                         \
                       gA + (size_t)_r * lda + (size_t)(t) * BK + _c * 4);     \
        }                                                                      \
        const uint32_t _sb = _s + A_TILE_WORDS * 4;                            \
        _Pragma("unroll")                                                      \
        for (int _q = 0; _q < 4; _q++) {                                       \
            const int _id = tid + _q * NTHREADS;                               \
            const int _r = _id >> 3, _c = _id & 7;                             \
            CP_ASYNC16(_sb + _r * (KPAD * 4) + _c * 16,                        \
                       gB + (size_t)_r * ldb + (size_t)(t) * BK + _c * 4);     \
        }                                                                      \
        CP_ASYNC_COMMIT();                                                     \
    } while (0)

    LOAD_STAGE(0);
    LOAD_STAGE(1);

    for (int t = 0; t < T; t++) {
        CP_ASYNC_WAIT1();
        __syncthreads();

        if (t + 2 < T) { LOAD_STAGE(t + 2); } else { CP_ASYNC_COMMIT(); }

        const uint32_t st = sbase + (t % NSTAGE) * (STAGE_WORDS * 4);

        #pragma unroll
        for (int k0 = 0; k0 < BK; k0 += 8) {
            const uint32_t kb = (uint32_t)(k0 * 4);
            uint32_t af[4][4], bf[4][2];
            #pragma unroll
            for (int i = 0; i < 4; i++)
                LDSM_X4(af[i][0], af[i][1], af[i][2], af[i][3],
                        st + a_off[i] + kb);
            #pragma unroll
            for (int jj = 0; jj < 2; jj++)
                LDSM_X4(bf[jj * 2][0], bf[jj * 2][1],
                        bf[jj * 2 + 1][0], bf[jj * 2 + 1][1],
                        st + b_off[jj] + kb);
            #pragma unroll
            for (int i = 0; i < 4; i++)
                #pragma unroll
                for (int q = 0; q < 4; q++) af[i][q] = rna(af[i][q]);
            #pragma unroll
            for (int j = 0; j < 4; j++) {
                bf[j][0] = rna(bf[j][0]);
                bf[j][1] = rna(bf[j][1]);
            }
            #pragma unroll
            for (int i = 0; i < 4; i++)
                #pragma unroll
                for (int j = 0; j < 4; j++)
                    MMA_TF32(acc[i][j], af[i], bf[j]);
        }
    }
    #undef LOAD_STAGE

    #pragma unroll
    for (int j = 0; j < 4; j++) {
        const int col = n0 + wn * 32 + j * 8 + tg * 2;
        const float2 bb = *(const float2*)(bias + col);
        #pragma unroll
        for (int i = 0; i < 4; i++) {
            const int r0 = m0 + wm * 64 + i * 16 + g;
            float2 v0; v0.x = acc[i][j][0] + bb.x; v0.y = acc[i][j][1] + bb.y;
            *(float2*)(C + (size_t)r0 * ldc + col) = v0;
            float2 v1; v1.x = acc[i][j][2] + bb.x; v1.y = acc[i][j][3] + bb.y;
            *(float2*)(C + (size_t)(r0 + 8) * ldc + col) = v1;
        }
    }
}

// ------------------------------- launch ------------------------------------
extern "C" void kernel_launch(void* const* d_in, const int* in_sizes, int n_in,
                              void* d_out, int out_size)
{
    const float* x        = (const float*)d_in[0];
    const float* h        = (const float*)d_in[1];
    const float* conv_buf = (const float*)d_in[2];
    const float* W_in     = (const float*)d_in[3];
    const float* b_in     = (const float*)d_in[4];
    const float* conv_w   = (const float*)d_in[5];
    const float* conv_b   = (const float*)d_in[6];
    const float* W_out    = (const float*)d_in[7];
    const float* b_out    = (const float*)d_in[8];

    const int D = in_sizes[6];
    const int B = in_sizes[0] / D;

    float* out      = (float*)d_out;
    float* out_hnew = out + (size_t)B * D;
    float* out_nbuf = out + (size_t)2 * B * D;

    cudaFuncSetAttribute(gemm1_fused,
                         cudaFuncAttributeMaxDynamicSharedMemorySize, SMEM_BYTES);
    cudaFuncSetAttribute(gemm_tf32,
                         cudaFuncAttributeMaxDynamicSharedMemorySize, SMEM_BYTES);

    // GEMM1 + fused elementwise: writes h_new, new_buf, g
    {
        dim3 grid(D / 128, B / BM);     // (8, 64)
        gemm1_fused<<<grid, NTHREADS, SMEM_BYTES>>>(
            x, W_in, b_in, h, conv_buf, conv_w, conv_b,
            out_hnew, out_nbuf, g_g);
    }

    // GEMM2: out = g @ W_out^T + b_out  [B, D]
    {
        dim3 grid(D / BN, B / BM);      // (4, 64)
        gemm_tf32<<<grid, NTHREADS, SMEM_BYTES>>>(g_g, D, W_out, D, b_out,
                                                  out, D, D);
    }
}